// round 5
// baseline (speedup 1.0000x reference)
#include <cuda_runtime.h>

#define NV 32
#define N2 1024
#define N3 32768
#define N4 1048576
#define MB 16   // n*d = 2*8
#define SOUT 8

// Scratch (static device memory; no allocation).
// r3 kept-axes order: 0=(i,j,k) 1=(i,j,l) 2=(i,k,l) 3=(j,k,l)
__device__ __align__(16) float g_r3[4][MB][N3];
// r_kl rows (only r2 persisted; others are transient in k_smallA)
__device__ __align__(16) float g_r2kl[MB][N2];
// r1 raw: 0=r_i 1=r_j 2=r_k  (r_l derived in k_smallB)
__device__ __align__(16) float g_r1raw[3][MB][NV];
// channel-mixed B-grouped tables
__device__ __align__(16) float g_g3[4][2][SOUT][N3];
__device__ __align__(16) float g_g2[6][2][SOUT][N2];
__device__ __align__(16) float g_g1[4][2][SOUT][NV];

// ---------------------------------------------------------------------------
// K1: block per (m,i). ONE pass over x[m,i,:,:,:], ONE __syncthreads.
// Produces r3[0]=r_ijk, r3[1]=r_ijl, r3[2]=r_ikl.
// ---------------------------------------------------------------------------
__global__ void __launch_bounds__(256) k_pass1(const float* __restrict__ x) {
    int m = blockIdx.x >> 5, i = blockIdx.x & 31;
    int t = threadIdx.x, w = t >> 5, lane = t & 31;
    int l4 = lane & 7;

    __shared__ float4 scol[8][32][8];   // [w][j][l4] per-warp column partials (32KB)
    __shared__ float  srow[32][32];     // [j][k] row sums (4KB)

    float4 acc; acc.x = acc.y = acc.z = acc.w = 0.f;
    const float4* xb = reinterpret_cast<const float4*>(x) + (size_t)(m * 32 + i) * (N3 / 4);

    for (int jo = 0; jo < 32; jo += 4) {
        float4 vv[4];
#pragma unroll
        for (int u = 0; u < 4; ++u) vv[u] = __ldg(xb + (jo + u) * 256 + t);
#pragma unroll
        for (int u = 0; u < 4; ++u) {
            int j = jo + u;
            float4 v = vv[u];
            acc.x += v.x; acc.y += v.y; acc.z += v.z; acc.w += v.w;

            // row sum over l (8-lane groups share one k)
            float s = v.x + v.y + v.z + v.w;
            s += __shfl_down_sync(0xffffffffu, s, 4, 8);
            s += __shfl_down_sync(0xffffffffu, s, 2, 8);
            s += __shfl_down_sync(0xffffffffu, s, 1, 8);
            if (l4 == 0) srow[j][t >> 3] = s;

            // column partial: sum over this warp's 4 k values
            float4 c = v;
            c.x += __shfl_xor_sync(0xffffffffu, c.x, 8);
            c.y += __shfl_xor_sync(0xffffffffu, c.y, 8);
            c.z += __shfl_xor_sync(0xffffffffu, c.z, 8);
            c.w += __shfl_xor_sync(0xffffffffu, c.w, 8);
            c.x += __shfl_xor_sync(0xffffffffu, c.x, 16);
            c.y += __shfl_xor_sync(0xffffffffu, c.y, 16);
            c.z += __shfl_xor_sync(0xffffffffu, c.z, 16);
            c.w += __shfl_xor_sync(0xffffffffu, c.w, 16);
            if (lane < 8) scol[w][j][lane] = c;
        }
    }
    __syncthreads();

    // r_ikl (complete: summed over j in registers)
    reinterpret_cast<float4*>(g_r3[2][m])[i * 256 + t] = acc;
    // r_ijk
    reinterpret_cast<float4*>(g_r3[0][m] + i * N2)[t] = reinterpret_cast<float4*>(srow)[t];
    // r_ijl: combine the 8 per-warp column partials
    {
        int j = t >> 3, q = t & 7;
        float4 rv = scol[0][j][q];
#pragma unroll
        for (int ww = 1; ww < 8; ++ww) {
            float4 cc = scol[ww][j][q];
            rv.x += cc.x; rv.y += cc.y; rv.z += cc.z; rv.w += cc.w;
        }
        reinterpret_cast<float4*>(g_r3[1][m] + i * N2)[t] = rv;
    }
}

// ---------------------------------------------------------------------------
// K2: second x pass (float2, L2-hot right after pass1). Thread per (n, 2 tt).
// Computes r_jkl on the fly and produces all four g3 tables in one shot.
// ---------------------------------------------------------------------------
__global__ void __launch_bounds__(256) k_pass2(const float* __restrict__ x,
                                               const float* __restrict__ coefs) {
    __shared__ float C[4][4][64];   // [A][B][d*8+so]
    int t = threadIdx.x;
    for (int e = t; e < 1024; e += 256) {
        int a = e >> 8, b = (e >> 6) & 3, ds = e & 63;
        int d = ds >> 3, so = ds & 7;
        C[a][b][ds] = coefs[d * 552 + so * 69 + 52 + a * 4 + b];
    }
    __syncthreads();

    int g = blockIdx.x * 256 + t;             // 0..32767
    int n = g >> 14, tt2 = g & 16383;         // float2 index into N3/2
    const float2* xb = reinterpret_cast<const float2*>(x) + (size_t)n * 8 * (N4 / 2) + tt2;

    float2 rj[8];
#pragma unroll
    for (int d = 0; d < 8; ++d) { rj[d].x = 0.f; rj[d].y = 0.f; }
#pragma unroll 4
    for (int i = 0; i < 32; ++i) {
#pragma unroll
        for (int d = 0; d < 8; ++d) {
            float2 v = __ldg(xb + (size_t)d * (N4 / 2) + i * (N3 / 2));
            rj[d].x += v.x; rj[d].y += v.y;
        }
    }
#pragma unroll
    for (int d = 0; d < 8; ++d)
        reinterpret_cast<float2*>(g_r3[3][n * 8 + d])[tt2] = rj[d];

    float2 acc[32];
#pragma unroll
    for (int q = 0; q < 32; ++q) { acc[q].x = 0.f; acc[q].y = 0.f; }
#pragma unroll
    for (int a = 0; a < 4; ++a) {
        float2 vd[8];
#pragma unroll
        for (int d = 0; d < 8; ++d)
            vd[d] = (a == 3) ? rj[d]
                  : __ldg(reinterpret_cast<const float2*>(g_r3[a][n * 8 + d]) + tt2);
#pragma unroll
        for (int b = 0; b < 4; ++b)
#pragma unroll
            for (int so = 0; so < 8; ++so) {
                float sx = 0.f, sy = 0.f;
#pragma unroll
                for (int d = 0; d < 8; ++d) {
                    float c = C[a][b][d * 8 + so];
                    sx += c * vd[d].x; sy += c * vd[d].y;
                }
                acc[b * 8 + so].x += sx; acc[b * 8 + so].y += sy;
            }
    }
#pragma unroll
    for (int b = 0; b < 4; ++b)
#pragma unroll
        for (int so = 0; so < 8; ++so)
            reinterpret_cast<float2*>(g_g3[b][n][so])[tt2] = acc[b * 8 + so];
}

// ---------------------------------------------------------------------------
// SA: block per (n, hi). Recomputes all 6 r2 values transiently from
// L2-resident r3, mixes to g2 immediately, emits r_i/r_j/r_k via warp
// reductions, persists the r_kl row for k_smallB.
// ---------------------------------------------------------------------------
__global__ void __launch_bounds__(256) k_smallA(const float* __restrict__ coefs) {
    int n = blockIdx.x >> 5, hi = blockIdx.x & 31;
    int t = threadIdx.x, d = t >> 5, tl = t & 31;
    int m = n * 8 + d;

    __shared__ float4 CT[6][8][8][2];   // [a][d][so][{b0..3},{b4,b5,_,_}]  (12KB)
    __shared__ float r2v[6][8][32];     // transient r2 slice (6KB)

    for (int e = t; e < 3072; e += 256) {
        int a = e >> 9, r = e & 511;
        int dd = r >> 6, so = (r >> 3) & 7, bq = r & 7;
        reinterpret_cast<float*>(CT)[((a * 8 + dd) * 8 + so) * 8 + bq] =
            (bq < 6) ? __ldg(&coefs[dd * 552 + so * 69 + 16 + a * 6 + bq]) : 0.f;
    }

    float s0, s1, s2, s3, s4, s5;
    {   // a=0: r_ij(hi,tl) = sum_k r3[0][hi*1024 + tl*32 + k]  (contiguous)
        const float4* p = reinterpret_cast<const float4*>(g_r3[0][m] + hi * N2 + tl * 32);
        float4 a4 = {0.f, 0.f, 0.f, 0.f};
#pragma unroll
        for (int u = 0; u < 8; ++u) {
            float4 v = __ldg(p + u);
            a4.x += v.x; a4.y += v.y; a4.z += v.z; a4.w += v.w;
        }
        s0 = a4.x + a4.y + a4.z + a4.w;
    }
    s1 = s2 = s3 = s4 = s5 = 0.f;
#pragma unroll
    for (int u = 0; u < 32; ++u) {
        s1 += __ldg(&g_r3[0][m][hi * N2 + u * 32 + tl]);   // r_ik: sum_j
        s2 += __ldg(&g_r3[1][m][hi * N2 + u * 32 + tl]);   // r_il: sum_j
        s3 += __ldg(&g_r3[0][m][u * N2 + hi * 32 + tl]);   // r_jk: sum_i
        s4 += __ldg(&g_r3[1][m][u * N2 + hi * 32 + tl]);   // r_jl: sum_i
        s5 += __ldg(&g_r3[2][m][u * N2 + hi * 32 + tl]);   // r_kl: sum_i
    }

    // r1 emissions via warp reductions (warp == one d, lanes == tl)
    float w0 = s0, w1 = s3, w2 = s5;
#pragma unroll
    for (int o = 16; o > 0; o >>= 1) {
        w0 += __shfl_down_sync(0xffffffffu, w0, o);
        w1 += __shfl_down_sync(0xffffffffu, w1, o);
        w2 += __shfl_down_sync(0xffffffffu, w2, o);
    }
    if (tl == 0) {
        g_r1raw[0][m][hi] = w0;   // r_i
        g_r1raw[1][m][hi] = w1;   // r_j
        g_r1raw[2][m][hi] = w2;   // r_k
    }
    g_r2kl[m][hi * 32 + tl] = s5;

    r2v[0][d][tl] = s0; r2v[1][d][tl] = s1; r2v[2][d][tl] = s2;
    r2v[3][d][tl] = s3; r2v[4][d][tl] = s4; r2v[5][d][tl] = s5;
    __syncthreads();

    // g2 mix: thread = (tl', so)
    int tlp = t >> 3, so = t & 7;
    float b0 = 0.f, b1 = 0.f, b2 = 0.f, b3 = 0.f, b4 = 0.f, b5 = 0.f;
#pragma unroll
    for (int a = 0; a < 6; ++a)
#pragma unroll
        for (int dd = 0; dd < 8; ++dd) {
            float v = r2v[a][dd][tlp];
            float4 c0 = CT[a][dd][so][0];
            float4 c1 = CT[a][dd][so][1];
            b0 += v * c0.x; b1 += v * c0.y; b2 += v * c0.z;
            b3 += v * c0.w; b4 += v * c1.x; b5 += v * c1.y;
        }
    int tt = hi * 32 + tlp;
    g_g2[0][n][so][tt] = b0; g_g2[1][n][so][tt] = b1;
    g_g2[2][n][so][tt] = b2; g_g2[3][n][so][tt] = b3;
    g_g2[4][n][so][tt] = b4; g_g2[5][n][so][tt] = b5;
}

// ---------------------------------------------------------------------------
// SB: block per n. r_l from r_kl; g1 mix with 256 threads.
// ---------------------------------------------------------------------------
__global__ void __launch_bounds__(256) k_smallB(const float* __restrict__ coefs) {
    int n = blockIdx.x;
    int t = threadIdx.x, d = t >> 5, v = t & 31;
    int m = n * 8 + d;

    __shared__ float C1[4][4][64];
    __shared__ float sr1[4][8][32];

    for (int e = t; e < 1024; e += 256) {
        int a = e >> 8, b = (e >> 6) & 3, ds = e & 63;
        int dd = ds >> 3, so = ds & 7;
        C1[a][b][ds] = __ldg(&coefs[dd * 552 + so * 69 + a * 4 + b]);
    }

    float s = 0.f;
#pragma unroll
    for (int k = 0; k < 32; ++k) s += __ldg(&g_r2kl[m][k * 32 + v]);
    sr1[3][d][v] = s;                              // r_l
    sr1[0][d][v] = __ldg(&g_r1raw[0][m][v]);       // r_i
    sr1[1][d][v] = __ldg(&g_r1raw[1][m][v]);       // r_j
    sr1[2][d][v] = __ldg(&g_r1raw[2][m][v]);       // r_k
    __syncthreads();

    int vv = t >> 3, so = t & 7;
    float b0 = 0.f, b1 = 0.f, b2 = 0.f, b3 = 0.f;
#pragma unroll
    for (int a = 0; a < 4; ++a)
#pragma unroll
        for (int dd = 0; dd < 8; ++dd) {
            float val = sr1[a][dd][vv];
            b0 += C1[a][0][dd * 8 + so] * val;
            b1 += C1[a][1][dd * 8 + so] * val;
            b2 += C1[a][2][dd * 8 + so] * val;
            b3 += C1[a][3][dd * 8 + so] * val;
        }
    g_g1[0][n][so][vv] = b0; g_g1[1][n][so][vv] = b1;
    g_g1[2][n][so][vv] = b2; g_g1[3][n][so][vv] = b3;
}

// ---------------------------------------------------------------------------
// Kf: final assembly. Block per (n, i, j-quad); loops 8 j's with zero syncs
// inside the loop. Dynamic smem 49408B.
// ---------------------------------------------------------------------------
__global__ void __launch_bounds__(256, 2) k_final(const float* __restrict__ x,
                                                  const float* __restrict__ coefs,
                                                  const float* __restrict__ bias,
                                                  float* __restrict__ out) {
    extern __shared__ __align__(16) char sm[];
    float4* sV = reinterpret_cast<float4*>(sm);                 // [8][256]
    float (*P8)[8][32] = reinterpret_cast<float(*)[8][32]>(sm + 32768);
    float (*Q8)[8][32] = reinterpret_cast<float(*)[8][32]>(sm + 40960);
    float (*cf)[8]     = reinterpret_cast<float(*)[8]>(sm + 49152);

    int bid = blockIdx.x;
    int n = bid >> 7, i = (bid >> 2) & 31, jq = bid & 3;
    int t = threadIdx.x, k = t >> 3, lq = t & 7;

#pragma unroll
    for (int so = 0; so < 8; ++so) {
        float4 a = __ldg(reinterpret_cast<const float4*>(g_g3[2][n][so]) + i * 256 + t);
        float4 b = __ldg(reinterpret_cast<const float4*>(g_g2[5][n][so]) + t);
        a.x += b.x; a.y += b.y; a.z += b.z; a.w += b.w;
        sV[so * 256 + t] = a;
    }
    if (t < 64) cf[t >> 3][t & 7] = coefs[(t >> 3) * 552 + (t & 7) * 69 + 68];
    {
        int jj = t >> 5, kk = t & 31;
        int j = jq * 8 + jj, ij = i * 32 + j;
#pragma unroll
        for (int so = 0; so < 8; ++so) {
            P8[jj][so][kk] = __ldg(&g_g3[0][n][so][ij * 32 + kk])
                           + __ldg(&g_g2[3][n][so][j * 32 + kk])
                           + __ldg(&g_g2[1][n][so][i * 32 + kk])
                           + __ldg(&g_g1[2][n][so][kk])
                           + __ldg(&g_g2[0][n][so][ij])
                           + __ldg(&g_g1[0][n][so][i])
                           + __ldg(&g_g1[1][n][so][j])
                           + __ldg(&bias[so]);
            Q8[jj][so][kk] = __ldg(&g_g3[1][n][so][ij * 32 + kk])
                           + __ldg(&g_g2[4][n][so][j * 32 + kk])
                           + __ldg(&g_g2[2][n][so][i * 32 + kk])
                           + __ldg(&g_g1[3][n][so][kk]);
        }
    }
    __syncthreads();

    const float4* xb = reinterpret_cast<const float4*>(x);
    float4* ob = reinterpret_cast<float4*>(out);

    for (int jj = 0; jj < 8; ++jj) {
        int j = jq * 8 + jj;
        int plane = (i * 32 + j) * 256 + t;

        float4 xv[8];
#pragma unroll
        for (int d = 0; d < 8; ++d)
            xv[d] = __ldg(xb + (size_t)(n * 8 + d) * (N4 / 4) + plane);
        float4 a4[8];
#pragma unroll
        for (int so = 0; so < 8; ++so)
            a4[so] = __ldg(reinterpret_cast<const float4*>(g_g3[3][n][so]) + j * 256 + t);

#pragma unroll
        for (int so = 0; so < 8; ++so) {
            float4 v1 = sV[so * 256 + t];
            float base = P8[jj][so][k];
            float4 q = *reinterpret_cast<const float4*>(&Q8[jj][so][lq * 4]);

            float4 acc;
            acc.x = base + q.x + v1.x + a4[so].x;
            acc.y = base + q.y + v1.y + a4[so].y;
            acc.z = base + q.z + v1.z + a4[so].z;
            acc.w = base + q.w + v1.w + a4[so].w;
#pragma unroll
            for (int d = 0; d < 8; ++d) {
                float c = cf[d][so];
                acc.x += c * xv[d].x;
                acc.y += c * xv[d].y;
                acc.z += c * xv[d].z;
                acc.w += c * xv[d].w;
            }
            ob[(size_t)(n * 8 + so) * (N4 / 4) + plane] = acc;
        }
    }
}

extern "C" void kernel_launch(void* const* d_in, const int* in_sizes, int n_in,
                              void* d_out, int out_size) {
    const float* x     = (const float*)d_in[0];
    const float* coefs = (const float*)d_in[1];
    const float* bias  = (const float*)d_in[2];
    float* out = (float*)d_out;

    cudaFuncSetAttribute(k_final, cudaFuncAttributeMaxDynamicSharedMemorySize, 49408);

    k_pass1<<<512, 256>>>(x);            // r3[0..2]
    k_pass2<<<128, 256>>>(x, coefs);     // r3[3] + all g3 tables (x L2-hot)
    k_smallA<<<64, 256>>>(coefs);        // transient r2 -> g2, r_i/r_j/r_k, r_kl
    k_smallB<<<2, 256>>>(coefs);         // r_l + g1
    k_final<<<256, 256, 49408>>>(x, coefs, bias, out);
}